// round 9
// baseline (speedup 1.0000x reference)
#include <cuda_runtime.h>
#include <cuda_bf16.h>
#include <math.h>
#include <stdint.h>

#define MAXN 100000
#define MAXE 800000
#define FD 64
#define BN_EPS 1e-5f

typedef unsigned long long ULL;

// ---------------- scratch (no allocations allowed) ----------------
__device__ int   g_cnt[MAXN];
__device__ int   g_off[MAXN + 1];
__device__ int   g_cursor[MAXN];
__device__ int   g_bsum[512];
__device__ float g_dis[MAXN];
__device__ ULL   g_csr[MAXE];     // packed {src:int, norm:float}
__device__ float g_H[(size_t)MAXN * FD];
__device__ float g_G[(size_t)MAXN * FD];
__device__ float g_Wm[FD * FD];   // W3 @ pW1 fp32
// W fragments in mma B-operand layout: slot 0=W1, 1=W2, 2=Wm, 3=pW2
// index: [(ks*8 + nt)*32 + lane]; .x = {k0,k0+1}, .y = {k0+8,k0+9} bf16x2
__device__ uint2 g_wfH[4][1024];
__device__ uint2 g_wfL[4][1024];
__device__ float g_scale1[FD], g_shift1[FD];
__device__ float g_scale2[FD], g_shift2[FD];
__device__ float g_fb[FD];
__device__ int   g_is64;

// ---------------- init: zero counts + edge dtype detect ----------------
__global__ void k_init(const unsigned int* ei, int n) {
    int i = blockIdx.x * blockDim.x + threadIdx.x;
    if (i < n) g_cnt[i] = 0;
    if (i == 0) {
        int is64 = 1;
        for (int j = 1; j < 64; j += 2)
            if (ei[j] != 0u) { is64 = 0; break; }
        g_is64 = is64;
    }
}

__device__ __forceinline__ int load_idx(const void* ei, long long pos) {
    if (g_is64) return (int)((const long long*)ei)[pos];
    return ((const int*)ei)[pos];
}

__global__ void k_count(const void* ei, int E) {
    int e = blockIdx.x * blockDim.x + threadIdx.x;
    if (e >= E) return;
    int dst = load_idx(ei, (long long)E + e);
    atomicAdd(&g_cnt[dst], 1);
}

// ---------------- weight fragment split ----------------
__device__ __forceinline__ uint32_t packbf(float a, float b) {
    uint32_t r;
    asm("cvt.rn.bf16x2.f32 %0, %1, %2;" : "=r"(r) : "f"(b), "f"(a));  // lo=a, hi=b
    return r;
}
__device__ __forceinline__ float bfhi(float v) {
    return __bfloat162float(__float2bfloat16(v));
}

__device__ __forceinline__ void wsplit_one(const float* __restrict__ src, int slot,
                                           int tid) {
#pragma unroll
    for (int i = 0; i < 4; i++) {
        int t = tid + i * 256;              // 0..1023
        int ks = t >> 8, nt = (t >> 5) & 7, lane = t & 31;
        int k0 = ks * 16 + (lane & 3) * 2;
        int nn = nt * 8 + (lane >> 2);
        float v00 = src[k0 * FD + nn];
        float v01 = src[(k0 + 1) * FD + nn];
        float v10 = src[(k0 + 8) * FD + nn];
        float v11 = src[(k0 + 9) * FD + nn];
        float h00 = bfhi(v00), h01 = bfhi(v01), h10 = bfhi(v10), h11 = bfhi(v11);
        g_wfH[slot][t] = make_uint2(packbf(h00, h01), packbf(h10, h11));
        g_wfL[slot][t] = make_uint2(packbf(v00 - h00, v01 - h01),
                                    packbf(v10 - h10, v11 - h11));
    }
}

__global__ void k_wsplit3(const float* W1, const float* W2, const float* pW2) {
    const float* src = (blockIdx.x == 0) ? W1 : (blockIdx.x == 1) ? W2 : pW2;
    int slot = (blockIdx.x == 2) ? 3 : blockIdx.x;
    wsplit_one(src, slot, threadIdx.x);
}

__global__ void k_wsplit_wm() { wsplit_one(g_Wm, 2, threadIdx.x); }

// Wm = W3 @ pW1 (fp32, one block)
__global__ void k_mm64(const float* __restrict__ A, const float* __restrict__ B,
                       float* __restrict__ C) {
    __shared__ float Bs[FD * FD];
    int tid = threadIdx.x;
#pragma unroll
    for (int i = 0; i < 16; i++) Bs[tid + i * 256] = B[tid + i * 256];
    __syncthreads();
    int r = tid >> 2, c0 = (tid & 3) * 16;
    float acc[16];
#pragma unroll
    for (int j = 0; j < 16; j++) acc[j] = 0.f;
    for (int k = 0; k < FD; k++) {
        float a = A[r * FD + k];
#pragma unroll
        for (int j = 0; j < 16; j++) acc[j] = fmaf(a, Bs[k * FD + c0 + j], acc[j]);
    }
#pragma unroll
    for (int j = 0; j < 16; j++) C[r * FD + c0 + j] = acc[j];
}

// ---------------- constants: BN folds + fused predictor bias ----------------
__global__ void k_consts(const float* b1, const float* g1, const float* bb1,
                         const float* m1, const float* v1,
                         const float* b2, const float* g2, const float* bb2,
                         const float* m2, const float* v2,
                         const float* b3, const float* pW1, const float* pb1) {
    int c = threadIdx.x;
    if (c >= FD) return;
    if (blockIdx.x == 0) {
        float s = g1[c] * rsqrtf(v1[c] + BN_EPS);
        g_scale1[c] = s;
        g_shift1[c] = (b1[c] - m1[c]) * s + bb1[c];
    } else if (blockIdx.x == 1) {
        float s = g2[c] * rsqrtf(v2[c] + BN_EPS);
        g_scale2[c] = s;
        g_shift2[c] = (b2[c] - m2[c]) * s + bb2[c];
    } else {
        float s = pb1[c];
        for (int k = 0; k < FD; k++) s += b3[k] * pW1[k * FD + c];
        g_fb[c] = s;
    }
}

// ---------------- scans ----------------
__global__ void k_scan1(int n) {
    __shared__ int s[256];
    int i = blockIdx.x * 256 + threadIdx.x;
    int v = (i < n) ? g_cnt[i] : 0;
    if (i < n) g_dis[i] = rsqrtf((float)(v + 1));   // +1 self loop
    s[threadIdx.x] = v;
    __syncthreads();
#pragma unroll
    for (int off = 1; off < 256; off <<= 1) {
        int t = (threadIdx.x >= off) ? s[threadIdx.x - off] : 0;
        __syncthreads();
        s[threadIdx.x] += t;
        __syncthreads();
    }
    if (i < n) g_off[i + 1] = s[threadIdx.x];
    if (threadIdx.x == 255) g_bsum[blockIdx.x] = s[255];
}

__global__ void k_scan2(int nb) {
    __shared__ int s[512];
    int t = threadIdx.x;
    int v = (t < nb) ? g_bsum[t] : 0;
    s[t] = v;
    __syncthreads();
#pragma unroll
    for (int off = 1; off < 512; off <<= 1) {
        int u = (t >= off) ? s[t - off] : 0;
        __syncthreads();
        s[t] += u;
        __syncthreads();
    }
    if (t < nb) g_bsum[t] = s[t] - v;   // exclusive
}

__global__ void k_scan3(int n) {
    int i = blockIdx.x * blockDim.x + threadIdx.x;
    if (i < n) {
        int off = g_off[i + 1] + g_bsum[i >> 8];
        g_off[i + 1] = off;
        g_cursor[i] = off - g_cnt[i];
    }
    if (i == 0) g_off[0] = 0;
}

__global__ void k_fill(const void* ei, int E) {
    int e = blockIdx.x * blockDim.x + threadIdx.x;
    if (e >= E) return;
    int s = load_idx(ei, e);
    int d = load_idx(ei, (long long)E + e);
    float norm = g_dis[s] * g_dis[d];
    int pos = atomicAdd(&g_cursor[d], 1);
    g_csr[pos] = (ULL)(unsigned int)s | ((ULL)__float_as_uint(norm) << 32);
}

// ================= tensor-core GEMM (HMMA, preloaded W fragments) =================
// Y[n,64] = X[n,64] @ W[64,64] (+bias). 128-row tile, 256 threads (8 warps x 16 rows).
// X = Xhi + Xlo bf16 in smem (ldmatrix); W fragments hi/lo read directly from
// global (L1-resident 16KB, coalesced LDG.64). D = XhWh + XhWl + XlWh (fp32).

#define LDA 72
#define OFF_ALO (128 * LDA * 2)
#define TC_SMEM (2 * 128 * LDA * 2)     // 36864 B

__device__ __forceinline__ uint32_t smem_u32(const void* p) {
    uint32_t a;
    asm("{ .reg .u64 t; cvta.to.shared.u64 t, %1; cvt.u32.u64 %0, t; }"
        : "=r"(a) : "l"(p));
    return a;
}

__device__ __forceinline__ void ldmA(uint32_t addr, uint32_t r[4]) {
    asm volatile("ldmatrix.sync.aligned.m8n8.x4.shared.b16 {%0,%1,%2,%3}, [%4];"
                 : "=r"(r[0]), "=r"(r[1]), "=r"(r[2]), "=r"(r[3]) : "r"(addr));
}
__device__ __forceinline__ void hmma(float d[4], const uint32_t a[4],
                                     uint32_t b0, uint32_t b1) {
    asm volatile(
        "mma.sync.aligned.m16n8k16.row.col.f32.bf16.bf16.f32 "
        "{%0,%1,%2,%3}, {%4,%5,%6,%7}, {%8,%9}, {%0,%1,%2,%3};"
        : "+f"(d[0]), "+f"(d[1]), "+f"(d[2]), "+f"(d[3])
        : "r"(a[0]), "r"(a[1]), "r"(a[2]), "r"(a[3]), "r"(b0), "r"(b1));
}

// EPI: 0 = none, 1 = +bias
template <int EPI>
__global__ void __launch_bounds__(256)
k_gemm_mma(const float* __restrict__ X,
           const uint2* __restrict__ wh, const uint2* __restrict__ wl,
           const float* __restrict__ bias, float* __restrict__ Y, int n) {
    extern __shared__ char smem[];
    uint32_t sb = smem_u32(smem);
    int tid = threadIdx.x, w = tid >> 5, lane = tid & 31;
    int row0 = blockIdx.x * 128;

    // ---- X tile split -> smem [r][k], 1024 groups of 8 floats, 4/thread ----
#pragma unroll
    for (int i = 0; i < 4; i++) {
        int t = tid + i * 256;
        int r = t >> 3, g = t & 7;
        int row = row0 + r;
        float4 a = make_float4(0.f, 0.f, 0.f, 0.f), b = a;
        if (row < n) {
            const float4* xp = (const float4*)(X + (size_t)row * FD + g * 8);
            a = xp[0]; b = xp[1];
        }
        float f[8] = {a.x, a.y, a.z, a.w, b.x, b.y, b.z, b.w};
        uint32_t hi[4], lo[4];
#pragma unroll
        for (int p = 0; p < 4; p++) {
            float h0 = bfhi(f[2 * p]), h1 = bfhi(f[2 * p + 1]);
            hi[p] = packbf(h0, h1);
            lo[p] = packbf(f[2 * p] - h0, f[2 * p + 1] - h1);
        }
        int off = r * (LDA * 2) + g * 16;
        *(uint4*)(smem + off) = make_uint4(hi[0], hi[1], hi[2], hi[3]);
        *(uint4*)(smem + OFF_ALO + off) = make_uint4(lo[0], lo[1], lo[2], lo[3]);
    }
    __syncthreads();

    uint32_t aA = sb + ((w * 16 + (lane & 15)) * LDA + (lane >> 4) * 8) * 2;
    uint32_t aAl = aA + OFF_ALO;

    float acc[8][4];
#pragma unroll
    for (int i = 0; i < 8; i++)
#pragma unroll
        for (int j = 0; j < 4; j++) acc[i][j] = 0.f;

#pragma unroll
    for (int ks = 0; ks < 4; ks++) {
        uint32_t ah[4], al[4];
        ldmA(aA + ks * 32, ah);            // +16 bf16 cols per k-step
        ldmA(aAl + ks * 32, al);
        const uint2* whk = wh + ks * 256 + lane;
        const uint2* wlk = wl + ks * 256 + lane;
#pragma unroll
        for (int nt = 0; nt < 8; nt++) {
            uint2 bh = whk[nt * 32];
            uint2 bl = wlk[nt * 32];
            hmma(acc[nt], ah, bh.x, bh.y);
            hmma(acc[nt], ah, bl.x, bl.y);
            hmma(acc[nt], al, bh.x, bh.y);
        }
    }

    // epilogue: C layout m16n8.f32 — {c0,c1} at (lane/4, 2*(lane%4)), {c2,c3} at row+8
    int r0 = row0 + w * 16 + (lane >> 2);
    int cbase = (lane & 3) * 2;
#pragma unroll
    for (int half = 0; half < 2; half++) {
        int row = r0 + half * 8;
        if (row >= n) continue;
        float* yr = Y + (size_t)row * FD;
#pragma unroll
        for (int nt = 0; nt < 8; nt++) {
            int c = nt * 8 + cbase;
            float2 v = make_float2(acc[nt][2 * half], acc[nt][2 * half + 1]);
            if (EPI == 1) { v.x += bias[c]; v.y += bias[c + 1]; }
            *(float2*)(yr + c) = v;
        }
    }
}

// ---------------- gather aggregation (CSR), fused self-loop + epilogue ----------
// One warp per node; lane handles cols [2*lane, 2*lane+1].
// EPI: 0 = plain, 1 = BN1+ReLU, 2 = BN2+ReLU, 3 = tanh(. + fb)
template <int EPI>
__global__ void __launch_bounds__(256)
k_gather(const float* __restrict__ h, float* __restrict__ out, int n) {
    int node = (blockIdx.x * blockDim.x + threadIdx.x) >> 5;
    int lane = threadIdx.x & 31;
    if (node >= n) return;

    const float2* hp = (const float2*)h;
    float d = g_dis[node];
    float2 acc = hp[(size_t)node * 32 + lane];
    float s2 = d * d;
    acc.x *= s2; acc.y *= s2;

    int e = g_off[node], end = g_off[node + 1];

    for (; e + 4 <= end; e += 4) {
        ULL e0 = g_csr[e + 0];
        ULL e1 = g_csr[e + 1];
        ULL e2 = g_csr[e + 2];
        ULL e3 = g_csr[e + 3];
        float2 v0 = hp[(size_t)(unsigned)e0 * 32 + lane];
        float2 v1 = hp[(size_t)(unsigned)e1 * 32 + lane];
        float2 v2 = hp[(size_t)(unsigned)e2 * 32 + lane];
        float2 v3 = hp[(size_t)(unsigned)e3 * 32 + lane];
        float n0 = __uint_as_float((unsigned)(e0 >> 32));
        float n1 = __uint_as_float((unsigned)(e1 >> 32));
        float n2 = __uint_as_float((unsigned)(e2 >> 32));
        float n3 = __uint_as_float((unsigned)(e3 >> 32));
        acc.x = fmaf(v0.x, n0, acc.x); acc.y = fmaf(v0.y, n0, acc.y);
        acc.x = fmaf(v1.x, n1, acc.x); acc.y = fmaf(v1.y, n1, acc.y);
        acc.x = fmaf(v2.x, n2, acc.x); acc.y = fmaf(v2.y, n2, acc.y);
        acc.x = fmaf(v3.x, n3, acc.x); acc.y = fmaf(v3.y, n3, acc.y);
    }
    for (; e < end; e++) {
        ULL e0 = g_csr[e];
        float2 v0 = hp[(size_t)(unsigned)e0 * 32 + lane];
        float n0 = __uint_as_float((unsigned)(e0 >> 32));
        acc.x = fmaf(v0.x, n0, acc.x); acc.y = fmaf(v0.y, n0, acc.y);
    }

    int c = lane * 2;
    if (EPI == 1) {
        acc.x = fmaxf(fmaf(acc.x, g_scale1[c],     g_shift1[c]),     0.f);
        acc.y = fmaxf(fmaf(acc.y, g_scale1[c + 1], g_shift1[c + 1]), 0.f);
    } else if (EPI == 2) {
        acc.x = fmaxf(fmaf(acc.x, g_scale2[c],     g_shift2[c]),     0.f);
        acc.y = fmaxf(fmaf(acc.y, g_scale2[c + 1], g_shift2[c + 1]), 0.f);
    } else if (EPI == 3) {
        acc.x = tanhf(acc.x + g_fb[c]);
        acc.y = tanhf(acc.y + g_fb[c + 1]);
    }
    ((float2*)out)[(size_t)node * 32 + lane] = acc;
}

// ---------------- launch ----------------
extern "C" void kernel_launch(void* const* d_in, const int* in_sizes, int n_in,
                              void* d_out, int out_size) {
    const float* x    = (const float*)d_in[0];
    const void*  ei   = d_in[1];
    const float* W1   = (const float*)d_in[2];
    const float* b1   = (const float*)d_in[3];
    const float* W2   = (const float*)d_in[4];
    const float* b2   = (const float*)d_in[5];
    const float* W3   = (const float*)d_in[6];
    const float* b3   = (const float*)d_in[7];
    const float* bn1g = (const float*)d_in[8];
    const float* bn1b = (const float*)d_in[9];
    const float* bn1m = (const float*)d_in[10];
    const float* bn1v = (const float*)d_in[11];
    const float* bn2g = (const float*)d_in[12];
    const float* bn2b = (const float*)d_in[13];
    const float* bn2m = (const float*)d_in[14];
    const float* bn2v = (const float*)d_in[15];
    const float* pW1  = (const float*)d_in[16];
    const float* pb1  = (const float*)d_in[17];
    const float* pW2  = (const float*)d_in[18];
    const float* pb2  = (const float*)d_in[19];
    float* out = (float*)d_out;

    int n = in_sizes[0] / FD;
    int E = in_sizes[1] / 2;
    if (n > MAXN) n = MAXN;
    if (E > MAXE) E = MAXE;

    float *H, *G, *WM;
    uint2 *WFH, *WFL;
    cudaGetSymbolAddress((void**)&H,   g_H);
    cudaGetSymbolAddress((void**)&G,   g_G);
    cudaGetSymbolAddress((void**)&WM,  g_Wm);
    cudaGetSymbolAddress((void**)&WFH, g_wfH);
    cudaGetSymbolAddress((void**)&WFL, g_wfL);

    const int TB = 256;
    int gb_n   = (n + TB - 1) / TB;
    int gb_e   = (E + TB - 1) / TB;
    int ntiles = (n + 127) / 128;         // 128-row gemm tiles
    int gb_w   = (n + 7) / 8;             // gather blocks (8 warps/block)
    int nb     = (n + 255) / 256;         // scan blocks

    // 1..3: init / count / weight fragment split (W1, W2, pW2)
    k_init<<<gb_n, TB>>>((const unsigned int*)ei, n);
    k_count<<<gb_e, TB>>>(ei, E);
    k_wsplit3<<<3, TB>>>(W1, W2, pW2);

    // 4: GEMM1 (profiled launch) — independent of CSR
    k_gemm_mma<0><<<ntiles, TB, TC_SMEM>>>(x, WFH + 0, WFL + 0, nullptr, H, n);

    // 5..7: constants, Wm = W3 @ pW1, split into slot 2
    k_consts<<<3, FD>>>(b1, bn1g, bn1b, bn1m, bn1v,
                        b2, bn2g, bn2b, bn2m, bn2v,
                        b3, pW1, pb1);
    k_mm64<<<1, TB>>>(W3, pW1, WM);
    k_wsplit_wm<<<1, TB>>>();

    // 8..11: CSR build
    k_scan1<<<nb, 256>>>(n);
    k_scan2<<<1, 512>>>(nb);
    k_scan3<<<gb_n, TB>>>(n);
    k_fill<<<gb_e, TB>>>(ei, E);

    // layer 1 aggregation + BN1/ReLU
    k_gather<1><<<gb_w, TB>>>(H, G, n);

    // layer 2
    k_gemm_mma<0><<<ntiles, TB, TC_SMEM>>>(G, WFH + 1024, WFL + 1024, nullptr, H, n);
    k_gather<2><<<gb_w, TB>>>(H, G, n);

    // layer 3 + predictor-GEMM1 merged: T = tanh(agg(G @ Wm) + fb)
    k_gemm_mma<0><<<ntiles, TB, TC_SMEM>>>(G, WFH + 2048, WFL + 2048, nullptr, H, n);
    k_gather<3><<<gb_w, TB>>>(H, G, n);

    // predictor output GEMM
    k_gemm_mma<1><<<ntiles, TB, TC_SMEM>>>(G, WFH + 3072, WFL + 3072, pb2, out, n);
}